// round 3
// baseline (speedup 1.0000x reference)
#include <cuda_runtime.h>
#include <math.h>

#define NB   8
#define NT   500
#define NF   257
#define NC   8
#define NNUL 4
#define LOWF 5
#define HIGHF 70
#define NBAND (HIGHF-LOWF)     // 65
#define DCF_SIZE (NB*NT*NF*NNUL)

#define A_    0.35f
#define OMA   0.65f
#define AOVER 0.53846156f      // a/(1-a)

#define RECF 12                // [tr ti pw pad nr0 ni0 nr1 ni1 nr2 ni2 nr3 ni3]

// ---------------- scratch ----------------
__device__ float g_rec[(size_t)NB*NF*NT*RECF];   // 49.3 MB
__device__ float g_pre[NB*NT];
__device__ float g_aft[NB*NT*NNUL];

// =================== K1: beamform (smem weights, t-pairs) ====================
// block: (b, f-tile of 32, t-tile of 32). 256 threads: f_l = tid&31, slot = tid>>5.
// thread handles t pairs (t0+slot*2+16k, +1) for k=0,1.
#define FTILES 9
#define TTILES 16

__global__ __launch_bounds__(256, 4)
void k1_beamform(const float* __restrict__ in,
                 const int*   __restrict__ beam_id,
                 const float* __restrict__ tw,
                 const float* __restrict__ nw,
                 float* __restrict__ out) {
    __shared__ float wsm[80][32];   // [part*8+c][f_local]

    int tid = threadIdx.x;
    int gid = blockIdx.x * 256 + tid;
    if (gid < NB*NT)      g_pre[gid] = 0.0f;
    if (gid < NB*NT*NNUL) g_aft[gid] = 0.0f;

    int tc = blockIdx.x % TTILES;
    int ft = (blockIdx.x / TTILES) % FTILES;
    int b  = blockIdx.x / (TTILES*FTILES);
    int f0 = ft * 32;
    int t0 = tc * 32;

    int fl   = tid & 31;
    int slot = tid >> 5;
    int f    = f0 + fl;
    int beam = beam_id[b];

    // ---- stage weights into smem: 2560 floats, 10 per thread ----
    for (int i = tid; i < 2560; i += 256) {
        int w  = i >> 5;          // 0..79
        int fw = i & 31;
        int fg = f0 + fw;
        if (fg < NF) {
            int part = w >> 3;    // 0..9
            int c    = w & 7;
            float v;
            if (part < 2) {
                v = tw[((beam*2 + part)*NF + fg)*NC + c];
            } else {
                int n  = (part - 2) >> 1;
                int ri = (part - 2) & 1;
                v = nw[(((beam*NNUL + n)*2 + ri)*NF + fg)*NC + c];
            }
            wsm[w][fw] = v;
        }
    }
    __syncthreads();

    if (f >= NF) return;

    #pragma unroll
    for (int k = 0; k < 2; k++) {
        int ta = t0 + k*16 + slot*2;
        int tb = ta + 1;
        bool va = ta < NT, vb = tb < NT;
        if (!va) continue;

        float xra[8], xia[8], xrb[8], xib[8];
        {
            const float* pa = in + ((size_t)(b*NT + ta)*2 + 0)*(NF*NC) + f*NC;
            const float* qa = in + ((size_t)(b*NT + ta)*2 + 1)*(NF*NC) + f*NC;
            float4 v0 = ((const float4*)pa)[0], v1 = ((const float4*)pa)[1];
            float4 w0 = ((const float4*)qa)[0], w1 = ((const float4*)qa)[1];
            xra[0]=v0.x; xra[1]=v0.y; xra[2]=v0.z; xra[3]=v0.w;
            xra[4]=v1.x; xra[5]=v1.y; xra[6]=v1.z; xra[7]=v1.w;
            xia[0]=w0.x; xia[1]=w0.y; xia[2]=w0.z; xia[3]=w0.w;
            xia[4]=w1.x; xia[5]=w1.y; xia[6]=w1.z; xia[7]=w1.w;
        }
        if (vb) {
            const float* pb = in + ((size_t)(b*NT + tb)*2 + 0)*(NF*NC) + f*NC;
            const float* qb = in + ((size_t)(b*NT + tb)*2 + 1)*(NF*NC) + f*NC;
            float4 v0 = ((const float4*)pb)[0], v1 = ((const float4*)pb)[1];
            float4 w0 = ((const float4*)qb)[0], w1 = ((const float4*)qb)[1];
            xrb[0]=v0.x; xrb[1]=v0.y; xrb[2]=v0.z; xrb[3]=v0.w;
            xrb[4]=v1.x; xrb[5]=v1.y; xrb[6]=v1.z; xrb[7]=v1.w;
            xib[0]=w0.x; xib[1]=w0.y; xib[2]=w0.z; xib[3]=w0.w;
            xib[4]=w1.x; xib[5]=w1.y; xib[6]=w1.z; xib[7]=w1.w;
        } else {
            #pragma unroll
            for (int c = 0; c < 8; c++) { xrb[c]=0.f; xib[c]=0.f; }
        }

        float* ra = g_rec + ((size_t)(b*NF + f)*NT + ta)*RECF;
        float* rb = g_rec + ((size_t)(b*NF + f)*NT + tb)*RECF;

        // ---- target + power ----
        float tra=0.f, tia=0.f, trb=0.f, tib=0.f, pwa=0.f, pwb=0.f;
        #pragma unroll
        for (int c = 0; c < 8; c++) {
            float wr = wsm[c][fl], wi = wsm[8+c][fl];
            tra = fmaf(wr, xra[c], tra); tra = fmaf(-wi, xia[c], tra);
            tia = fmaf(wi, xra[c], tia); tia = fmaf( wr, xia[c], tia);
            trb = fmaf(wr, xrb[c], trb); trb = fmaf(-wi, xib[c], trb);
            tib = fmaf(wi, xrb[c], tib); tib = fmaf( wr, xib[c], tib);
            pwa = fmaf(xra[c], xra[c], pwa); pwa = fmaf(xia[c], xia[c], pwa);
            pwb = fmaf(xrb[c], xrb[c], pwb); pwb = fmaf(xib[c], xib[c], pwb);
        }
        pwa *= 0.125f; pwb *= 0.125f;

        ((float4*)ra)[0] = make_float4(tra, tia, pwa, 0.f);
        out[DCF_SIZE + ((size_t)(b*NT + ta)*2 + 0)*NF + f] = tra;
        out[DCF_SIZE + ((size_t)(b*NT + ta)*2 + 1)*NF + f] = tia;
        if (vb) {
            ((float4*)rb)[0] = make_float4(trb, tib, pwb, 0.f);
            out[DCF_SIZE + ((size_t)(b*NT + tb)*2 + 0)*NF + f] = trb;
            out[DCF_SIZE + ((size_t)(b*NT + tb)*2 + 1)*NF + f] = tib;
        }

        // ---- nulls (2 at a time -> one float4 store) ----
        #pragma unroll
        for (int g = 0; g < 2; g++) {
            float va4[4], vb4[4];
            #pragma unroll
            for (int h = 0; h < 2; h++) {
                int n = g*2 + h;
                float nra=0.f, nia=0.f, nrb=0.f, nib=0.f;
                #pragma unroll
                for (int c = 0; c < 8; c++) {
                    float wr = wsm[(2+2*n)*8 + c][fl];
                    float wi = wsm[(3+2*n)*8 + c][fl];
                    nra = fmaf(wr, xra[c], nra); nra = fmaf(-wi, xia[c], nra);
                    nia = fmaf(wi, xra[c], nia); nia = fmaf( wr, xia[c], nia);
                    nrb = fmaf(wr, xrb[c], nrb); nrb = fmaf(-wi, xib[c], nrb);
                    nib = fmaf(wi, xrb[c], nib); nib = fmaf( wr, xib[c], nib);
                }
                va4[h*2]=nra; va4[h*2+1]=nia;
                vb4[h*2]=nrb; vb4[h*2+1]=nib;
            }
            ((float4*)ra)[1+g] = make_float4(va4[0], va4[1], va4[2], va4[3]);
            if (vb) ((float4*)rb)[1+g] = make_float4(vb4[0], vb4[1], vb4[2], vb4[3]);
        }
    }
}

// =================== K2 common: decayed Kogge-Stone over 32 t ===============
__device__ __forceinline__ void load_u(const float* __restrict__ recb,
                                       int t, float u[9]) {
    const float* rp = recb + (size_t)t*RECF;
    float4 h   = ((const float4*)rp)[0];
    float4 n01 = ((const float4*)rp)[1];
    float4 n23 = ((const float4*)rp)[2];
    float tr = h.x, ti = h.y, pw = h.z;
    float nr[4] = {n01.x, n01.z, n23.x, n23.z};
    float ni[4] = {n01.y, n01.w, n23.y, n23.w};
    #pragma unroll
    for (int n = 0; n < 4; n++) {
        float pr = tr*nr[n] + ti*ni[n];
        float pi = ti*nr[n] - tr*ni[n];
        if (t == 0) {   // reference's t=0 quirk
            pr = fmaf( AOVER*ti, ni[n], pr);
            pi = fmaf(-AOVER*tr, ni[n], pi);
        }
        u[n]   = OMA*pr;
        u[4+n] = OMA*pi;
    }
    u[8] = OMA*pw;
}

__device__ __forceinline__ void scan9(float u[9], int lane) {
    const float AJ0=0.35f, AJ1=0.1225f, AJ2=0.01500625f,
                AJ3=2.25187539e-4f, AJ4=5.07094278e-8f;
    #pragma unroll
    for (int kk = 0; kk < 9; kk++) {
        float v;
        v = __shfl_up_sync(0xffffffffu, u[kk], 1);  if (lane>=1)  u[kk]=fmaf(AJ0,v,u[kk]);
        v = __shfl_up_sync(0xffffffffu, u[kk], 2);  if (lane>=2)  u[kk]=fmaf(AJ1,v,u[kk]);
        v = __shfl_up_sync(0xffffffffu, u[kk], 4);  if (lane>=4)  u[kk]=fmaf(AJ2,v,u[kk]);
        v = __shfl_up_sync(0xffffffffu, u[kk], 8);  if (lane>=8)  u[kk]=fmaf(AJ3,v,u[kk]);
        v = __shfl_up_sync(0xffffffffu, u[kk], 16); if (lane>=16) u[kk]=fmaf(AJ4,v,u[kk]);
    }
}

// =================== K2a: band sums only (f in [5,70)) ======================
__global__ void k2a_band(void) {
    int gtid = blockIdx.x * blockDim.x + threadIdx.x;
    int gw   = gtid >> 5;
    int lane = gtid & 31;
    if (gw >= NB*NBAND*2) return;

    int f     = LOWF + (gw % NBAND);
    int b     = (gw / NBAND) % NB;
    int chunk = gw / (NBAND*NB);

    const float* recb = g_rec + (size_t)(b*NF + f)*NT*RECF;
    float pa = exp2f((float)(lane+1) * -1.5145732f);

    float carry[9];
    #pragma unroll
    for (int kk = 0; kk < 9; kk++) carry[kk] = 0.0f;

    int T0    = chunk ? 224 : 0;
    int niter = chunk ? 9 : 8;

    for (int it = 0; it < niter; it++, T0 += 32) {
        bool wr = !(chunk && it == 0);
        int t  = T0 + lane;
        float u[9];
        load_u(recb, min(t, NT-1), u);
        scan9(u, lane);
        float y[9];
        #pragma unroll
        for (int kk = 0; kk < 9; kk++) y[kk] = fmaf(pa, carry[kk], u[kk]);
        #pragma unroll
        for (int kk = 0; kk < 9; kk++) carry[kk] = __shfl_sync(0xffffffffu, y[kk], 31);

        if (wr && t < NT) {
            float psd = y[8];
            atomicAdd(g_pre + b*NT + t, psd);
            float* aftp = g_aft + (b*NT + t)*NNUL;
            #pragma unroll
            for (int n = 0; n < 4; n++) {
                float ph = sqrtf(fmaf(y[n], y[n], y[4+n]*y[4+n]));
                atomicAdd(aftp + n, ph);
            }
        }
    }
}

// =================== K2b: full scan + ratio, writes final dcf ===============
__global__ void k2b_scan(float* __restrict__ out) {
    int gtid = blockIdx.x * blockDim.x + threadIdx.x;
    int gw   = gtid >> 5;
    int lane = gtid & 31;
    if (gw >= NB*NF*2) return;

    int f     = gw % NF;
    int b     = (gw / NF) % NB;
    int chunk = gw / (NF*NB);

    const float* recb = g_rec + (size_t)(b*NF + f)*NT*RECF;
    float* qout = out + (size_t)(b*NT)*NF*NNUL + f*NNUL;
    float pa = exp2f((float)(lane+1) * -1.5145732f);

    float carry[9];
    #pragma unroll
    for (int kk = 0; kk < 9; kk++) carry[kk] = 0.0f;

    int T0    = chunk ? 224 : 0;
    int niter = chunk ? 9 : 8;

    for (int it = 0; it < niter; it++, T0 += 32) {
        bool wr = !(chunk && it == 0);
        int t  = T0 + lane;
        float u[9];
        load_u(recb, min(t, NT-1), u);
        scan9(u, lane);
        float y[9];
        #pragma unroll
        for (int kk = 0; kk < 9; kk++) y[kk] = fmaf(pa, carry[kk], u[kk]);
        #pragma unroll
        for (int kk = 0; kk < 9; kk++) carry[kk] = __shfl_sync(0xffffffffu, y[kk], 31);

        if (wr && t < NT) {
            float psd  = y[8];
            float rinv = __fdividef(1.0f, psd + 1e-13f);
            float q[4];
            #pragma unroll
            for (int n = 0; n < 4; n++) {
                float ph = sqrtf(fmaf(y[n], y[n], y[4+n]*y[4+n]));
                q[n] = fminf(fmaxf(ph*rinv, 0.01f), 1.0f);
            }
            if (t > 0) {
                float pinv = __fdividef(1.0f, g_pre[b*NT + t] + 1e-10f);
                const float* aftp = g_aft + (b*NT + t)*NNUL;
                #pragma unroll
                for (int n = 0; n < 4; n++) {
                    float rat = fminf(fmaxf(aftp[n]*pinv, 0.01f), 1.0f);
                    q[n] = sqrtf(q[n]*rat);
                }
            }
            *(float4*)(qout + (size_t)t*NF*NNUL) = make_float4(q[0], q[1], q[2], q[3]);
        }
    }
}

// =================== launcher ===============================================
extern "C" void kernel_launch(void* const* d_in, const int* in_sizes, int n_in,
                              void* d_out, int out_size) {
    const float* in      = (const float*)d_in[0];
    const int*   beam_id = (const int*)  d_in[1];
    const float* tw      = (const float*)d_in[2];
    const float* nw      = (const float*)d_in[3];
    float* out = (float*)d_out;

    k1_beamform<<<NB*FTILES*TTILES, 256>>>(in, beam_id, tw, nw, out);

    {   int total = NB*NBAND*2*32;
        k2a_band<<<(total + 255)/256, 256>>>(); }

    {   int total = NB*NF*2*32;
        k2b_scan<<<(total + 255)/256, 256>>>(out); }
}

// round 4
// speedup vs baseline: 1.8065x; 1.8065x over previous
#include <cuda_runtime.h>
#include <math.h>

#define NB   8
#define NT   500
#define NF   257
#define NC   8
#define NNUL 4
#define LOWF 5
#define HIGHF 70
#define NBAND (HIGHF-LOWF)          // 65
#define DCF_SIZE (NB*NT*NF*NNUL)

#define OMA   0.65f
#define AOVER 0.53846156f           // a/(1-a)

// ---------------- scratch ----------------
__device__ float g_pre[NB*NT];
__device__ float g_aft[NB*NT*NNUL];
__device__ float g_targ[(size_t)NB*NF*NT*2];   // (b,f,t,{tr,ti}) coalesced

// ---------------- decayed Kogge-Stone over 32 lanes --------------------------
__device__ __forceinline__ void scan9(float u[9], int lane) {
    const float AJ0=0.35f, AJ1=0.1225f, AJ2=0.01500625f,
                AJ3=2.25187539e-4f, AJ4=5.07094278e-8f;
    #pragma unroll
    for (int kk = 0; kk < 9; kk++) {
        float v;
        v = __shfl_up_sync(0xffffffffu, u[kk], 1);  if (lane>=1)  u[kk]=fmaf(AJ0,v,u[kk]);
        v = __shfl_up_sync(0xffffffffu, u[kk], 2);  if (lane>=2)  u[kk]=fmaf(AJ1,v,u[kk]);
        v = __shfl_up_sync(0xffffffffu, u[kk], 4);  if (lane>=4)  u[kk]=fmaf(AJ2,v,u[kk]);
        v = __shfl_up_sync(0xffffffffu, u[kk], 8);  if (lane>=8)  u[kk]=fmaf(AJ3,v,u[kk]);
        v = __shfl_up_sync(0xffffffffu, u[kk], 16); if (lane>=16) u[kk]=fmaf(AJ4,v,u[kk]);
    }
}

// compute pr/pi/pw (premultiplied by 1-a) for one (b,f,t) point
// tw in registers (same for whole block, broadcast), nulls via volatile smem.
__device__ __forceinline__ void point_u(const float* __restrict__ in,
                                        volatile const float* wn,
                                        const float twr[8], const float twi[8],
                                        int b, int f, int t,
                                        float u[9], float& trO, float& tiO) {
    const float* xrp = in + ((size_t)(b*NT + t)*2 + 0)*(NF*NC) + f*NC;
    const float* xip = in + ((size_t)(b*NT + t)*2 + 1)*(NF*NC) + f*NC;
    float xr[8], xi[8];
    {
        float4 v0 = ((const float4*)xrp)[0], v1 = ((const float4*)xrp)[1];
        float4 w0 = ((const float4*)xip)[0], w1 = ((const float4*)xip)[1];
        xr[0]=v0.x; xr[1]=v0.y; xr[2]=v0.z; xr[3]=v0.w;
        xr[4]=v1.x; xr[5]=v1.y; xr[6]=v1.z; xr[7]=v1.w;
        xi[0]=w0.x; xi[1]=w0.y; xi[2]=w0.z; xi[3]=w0.w;
        xi[4]=w1.x; xi[5]=w1.y; xi[6]=w1.z; xi[7]=w1.w;
    }
    float tr=0.f, ti=0.f, pw=0.f;
    #pragma unroll
    for (int c = 0; c < 8; c++) {
        tr = fmaf(twr[c], xr[c], tr); tr = fmaf(-twi[c], xi[c], tr);
        ti = fmaf(twi[c], xr[c], ti); ti = fmaf( twr[c], xi[c], ti);
        pw = fmaf(xr[c], xr[c], pw);  pw = fmaf(xi[c], xi[c], pw);
    }
    pw *= 0.125f;
    trO = tr; tiO = ti;

    #pragma unroll
    for (int n = 0; n < NNUL; n++) {
        float nr=0.f, ni=0.f;
        #pragma unroll
        for (int c = 0; c < 8; c++) {
            float wr = wn[n*16 + c];
            float wi = wn[n*16 + 8 + c];
            nr = fmaf(wr, xr[c], nr); nr = fmaf(-wi, xi[c], nr);
            ni = fmaf(wi, xr[c], ni); ni = fmaf( wr, xi[c], ni);
        }
        float pr = tr*nr + ti*ni;
        float pi = ti*nr - tr*ni;
        if (t == 0) {   // reference's t=0 quirk
            pr = fmaf( AOVER*ti, ni, pr);
            pi = fmaf(-AOVER*tr, ni, pi);
        }
        u[n]   = OMA*pr;
        u[4+n] = OMA*pi;
    }
    u[8] = OMA*pw;
}

// stage weights: tw -> regs (broadcast loads), nulls -> smem
__device__ __forceinline__ void stage_w(const float* __restrict__ tw,
                                        const float* __restrict__ nw,
                                        int beam, int f, int tid,
                                        float* wn, float twr[8], float twi[8]) {
    if (tid < 64) {
        int part = tid >> 3;       // 0..7 : (n,ri)
        int n  = part >> 1;
        int ri = part & 1;
        int c  = tid & 7;
        wn[n*16 + ri*8 + c] = nw[(((beam*NNUL + n)*2 + ri)*NF + f)*NC + c];
    }
    const float* twrp = tw + ((beam*2 + 0)*NF + f)*NC;
    const float* twip = tw + ((beam*2 + 1)*NF + f)*NC;
    float4 a0 = ((const float4*)twrp)[0], a1 = ((const float4*)twrp)[1];
    float4 b0 = ((const float4*)twip)[0], b1 = ((const float4*)twip)[1];
    twr[0]=a0.x; twr[1]=a0.y; twr[2]=a0.z; twr[3]=a0.w;
    twr[4]=a1.x; twr[5]=a1.y; twr[6]=a1.z; twr[7]=a1.w;
    twi[0]=b0.x; twi[1]=b0.y; twi[2]=b0.z; twi[3]=b0.w;
    twi[4]=b1.x; twi[5]=b1.y; twi[6]=b1.z; twi[7]=b1.w;
    __syncthreads();
}

// =================== K0: zero band accumulators ==============================
__global__ void k0_zero(void) {
    int i = blockIdx.x*256 + threadIdx.x;
    if (i < NB*NT)      g_pre[i] = 0.0f;
    if (i < NB*NT*NNUL) g_aft[i] = 0.0f;
}

// =================== K2a: band sums (f in [5,70)), fused beamform+scan ======
__global__ __launch_bounds__(128)
void k2a_band(const float* __restrict__ in, const int* __restrict__ beam_id,
              const float* __restrict__ tw, const float* __restrict__ nw) {
    __shared__ float wn_s[64];
    int tid = threadIdx.x, lane = tid & 31, w = tid >> 5;
    int f = LOWF + blockIdx.x % NBAND;
    int b = blockIdx.x / NBAND;
    int beam = beam_id[b];

    float twr[8], twi[8];
    stage_w(tw, nw, beam, f, tid, wn_s, twr, twi);
    volatile const float* wn = wn_s;

    float pa = exp2f((float)(lane+1) * -1.5145732f);
    float carry[9];
    #pragma unroll
    for (int k = 0; k < 9; k++) carry[k] = 0.0f;

    int t0 = w * 128;
    for (int it = (w == 0 ? 0 : -1); it < 4; it++) {
        int t  = t0 + it*32 + lane;
        int tc = min(t, NT-1);
        float u[9], tr, ti;
        point_u(in, wn, twr, twi, b, f, tc, u, tr, ti);
        scan9(u, lane);
        float y[9];
        #pragma unroll
        for (int k = 0; k < 9; k++) y[k] = fmaf(pa, carry[k], u[k]);
        #pragma unroll
        for (int k = 0; k < 9; k++) carry[k] = __shfl_sync(0xffffffffu, y[k], 31);

        if (it >= 0 && t < NT) {
            atomicAdd(g_pre + b*NT + t, y[8]);
            float* aftp = g_aft + (b*NT + t)*NNUL;
            #pragma unroll
            for (int n = 0; n < NNUL; n++)
                atomicAdd(aftp + n, sqrtf(fmaf(y[n], y[n], y[4+n]*y[4+n])));
        }
    }
}

// =================== K1: fused beamform + scan + ratio -> final dcf =========
__global__ __launch_bounds__(128)
void k1_fused(const float* __restrict__ in, const int* __restrict__ beam_id,
              const float* __restrict__ tw, const float* __restrict__ nw,
              float* __restrict__ out) {
    __shared__ float wn_s[64];
    int tid = threadIdx.x, lane = tid & 31, w = tid >> 5;
    int f = blockIdx.x % NF;
    int b = blockIdx.x / NF;
    int beam = beam_id[b];

    float twr[8], twi[8];
    stage_w(tw, nw, beam, f, tid, wn_s, twr, twi);
    volatile const float* wn = wn_s;

    float pa = exp2f((float)(lane+1) * -1.5145732f);
    float carry[9];
    #pragma unroll
    for (int k = 0; k < 9; k++) carry[k] = 0.0f;

    int t0 = w * 128;
    for (int it = (w == 0 ? 0 : -1); it < 4; it++) {
        int t  = t0 + it*32 + lane;
        int tc = min(t, NT-1);
        float u[9], tr, ti;
        point_u(in, wn, twr, twi, b, f, tc, u, tr, ti);
        scan9(u, lane);
        float y[9];
        #pragma unroll
        for (int k = 0; k < 9; k++) y[k] = fmaf(pa, carry[k], u[k]);
        #pragma unroll
        for (int k = 0; k < 9; k++) carry[k] = __shfl_sync(0xffffffffu, y[k], 31);

        if (it >= 0 && t < NT) {
            float rinv = __fdividef(1.0f, y[8] + 1e-13f);
            float q[4];
            #pragma unroll
            for (int n = 0; n < NNUL; n++) {
                float ph = sqrtf(fmaf(y[n], y[n], y[4+n]*y[4+n]));
                q[n] = fminf(fmaxf(ph*rinv, 0.01f), 1.0f);
            }
            if (t > 0) {
                float pinv = __fdividef(1.0f, g_pre[b*NT + t] + 1e-10f);
                float4 af = ((const float4*)g_aft)[b*NT + t];
                q[0] = sqrtf(q[0] * fminf(fmaxf(af.x*pinv, 0.01f), 1.0f));
                q[1] = sqrtf(q[1] * fminf(fmaxf(af.y*pinv, 0.01f), 1.0f));
                q[2] = sqrtf(q[2] * fminf(fmaxf(af.z*pinv, 0.01f), 1.0f));
                q[3] = sqrtf(q[3] * fminf(fmaxf(af.w*pinv, 0.01f), 1.0f));
            }
            *(float4*)(out + ((size_t)(b*NT + t)*NF + f)*4) =
                make_float4(q[0], q[1], q[2], q[3]);
            // targ to coalesced scratch (b,f,t,{r,i})
            ((float2*)g_targ)[(size_t)(b*NF + f)*NT + t] = make_float2(tr, ti);
        }
    }
}

// =================== K4: targ transpose (b,f,t) -> (b,t,part,f) =============
#define FT_TILES 9
#define TT_TILES 16
__global__ __launch_bounds__(256)
void k4_targ(float* __restrict__ out) {
    __shared__ float2 sm[32][33];
    int tt = blockIdx.x % TT_TILES;
    int ft = (blockIdx.x / TT_TILES) % FT_TILES;
    int b  = blockIdx.x / (TT_TILES*FT_TILES);
    int f0 = ft*32, t0 = tt*32;
    int tid = tid = threadIdx.x;
    int l = tid & 31, r = tid >> 5;

    #pragma unroll
    for (int p = 0; p < 4; p++) {          // load: lanes along t
        int fr = r + p*8, t = t0 + l, f = f0 + fr;
        if (f < NF && t < NT)
            sm[fr][l] = ((const float2*)g_targ)[(size_t)(b*NF + f)*NT + t];
    }
    __syncthreads();
    #pragma unroll
    for (int p = 0; p < 4; p++) {          // store: lanes along f
        int trow = r + p*8, t = t0 + trow, f = f0 + l;
        if (f < NF && t < NT) {
            float2 v = sm[l][trow];
            out[DCF_SIZE + ((size_t)(b*NT + t)*2 + 0)*NF + f] = v.x;
            out[DCF_SIZE + ((size_t)(b*NT + t)*2 + 1)*NF + f] = v.y;
        }
    }
}

// =================== launcher ===============================================
extern "C" void kernel_launch(void* const* d_in, const int* in_sizes, int n_in,
                              void* d_out, int out_size) {
    const float* in      = (const float*)d_in[0];
    const int*   beam_id = (const int*)  d_in[1];
    const float* tw      = (const float*)d_in[2];
    const float* nw      = (const float*)d_in[3];
    float* out = (float*)d_out;

    k0_zero<<<(NB*NT*NNUL + 255)/256, 256>>>();
    k2a_band<<<NB*NBAND, 128>>>(in, beam_id, tw, nw);
    k1_fused<<<NB*NF, 128>>>(in, beam_id, tw, nw, out);
    k4_targ<<<NB*FT_TILES*TT_TILES, 256>>>(out);
}